// round 1
// baseline (speedup 1.0000x reference)
#include <cuda_runtime.h>
#include <math.h>

#define BB 16
#define CIN 256
#define CO 128
#define HH 32
#define WW 32
#define HO 64
#define WO 64
#define NOFF 27

// ---------------- scratch (static device globals; no allocation) ----------------
__device__ float g_off[BB * NOFF * HH * WW];   // offset-conv output (27 ch)
__device__ float g_y0[BB * CO * HH * WW];      // deform-conv output (pre-BN)
__device__ float g_y1[BB * CO * HO * WO];      // transposed-conv output (pre-BN)
__device__ float g_sc1[CO], g_sh1[CO];         // BN1 folded scale/shift
__device__ float g_sc2[CO], g_sh2[CO];         // BN2 folded scale/shift

// =================================================================================
// Kernel 1: offset conv 3x3, CIN=256 -> 27 channels.
// Block = (b, row i). Threads (32,8): tx = out-channel lane (27 active), ty = j-group
// (4 px each). Weights + x rows staged in SMEM per 16-channel chunk.
// =================================================================================
__global__ void k_offset(const float* __restrict__ x,
                         const float* __restrict__ w_off,
                         const float* __restrict__ b_off) {
    const int i  = blockIdx.x;
    const int b  = blockIdx.y;
    const int tx = threadIdx.x;        // oc lane
    const int ty = threadIdx.y;        // j group
    const int tid = ty * 32 + tx;

    __shared__ float xs[16][3][36];    // [c][row][col(-1..32)+pad]
    __shared__ float ws[16][9][32];    // [c][tap][oc]

    float a0 = 0.f, a1 = 0.f, a2 = 0.f, a3 = 0.f;

    for (int c0 = 0; c0 < CIN; c0 += 16) {
        // stage x: 16 ch x 3 rows x 34 cols
        for (int s = tid; s < 16 * 3 * 34; s += 256) {
            int c = s / 102, r = (s % 102) / 34, col = s % 34;
            int ii = i + r - 1, jj = col - 1;
            float v = 0.f;
            if (ii >= 0 && ii < HH && jj >= 0 && jj < WW)
                v = x[((b * CIN + c0 + c) * HH + ii) * WW + jj];
            xs[c][r][col] = v;
        }
        // stage w: 27 oc x 16 c x 9 taps
        for (int s = tid; s < 27 * 16 * 9; s += 256) {
            int oc = s / 144, c = (s % 144) / 9, tap = s % 9;
            ws[c][tap][oc] = w_off[(oc * CIN + c0 + c) * 9 + tap];
        }
        __syncthreads();

        const int tj = ty * 4;
#pragma unroll 4
        for (int c = 0; c < 16; c++) {
#pragma unroll
            for (int kh = 0; kh < 3; kh++) {
                float x0 = xs[c][kh][tj + 0];
                float x1 = xs[c][kh][tj + 1];
                float x2 = xs[c][kh][tj + 2];
                float x3 = xs[c][kh][tj + 3];
                float x4 = xs[c][kh][tj + 4];
                float x5 = xs[c][kh][tj + 5];
                float w0 = ws[c][kh * 3 + 0][tx];
                float w1 = ws[c][kh * 3 + 1][tx];
                float w2 = ws[c][kh * 3 + 2][tx];
                a0 = fmaf(x0, w0, fmaf(x1, w1, fmaf(x2, w2, a0)));
                a1 = fmaf(x1, w0, fmaf(x2, w1, fmaf(x3, w2, a1)));
                a2 = fmaf(x2, w0, fmaf(x3, w1, fmaf(x4, w2, a2)));
                a3 = fmaf(x3, w0, fmaf(x4, w1, fmaf(x5, w2, a3)));
            }
        }
        __syncthreads();
    }
    if (tx < NOFF) {
        float bo = b_off[tx];
        float4 r = make_float4(a0 + bo, a1 + bo, a2 + bo, a3 + bo);
        *(float4*)&g_off[((b * NOFF + tx) * HH + i) * WW + ty * 4] = r;
    }
}

// =================================================================================
// Kernel 2: deformable conv. Block = (b, 2 rows = 64 px). GEMM [64px,2304]x[2304,128]
// with A built by on-the-fly bilinear sampling. Corner idx/weights (incl. sigmoid
// mask) precomputed once per block. b_dcn omitted (cancels exactly in BN1).
// =================================================================================
__global__ void __launch_bounds__(256) k_deform(const float* __restrict__ x,
                                                const float* __restrict__ w_dcn) {
    const int b  = blockIdx.y;
    const int i0 = blockIdx.x * 2;
    const int tid = threadIdx.x;

    __shared__ float sm[11648];                 // 46.6 KB, aliased regions
    int4*   idxs = (int4*)sm;                   // 576 entries  -> floats [0,2304)
    float4* wgts = (float4*)(sm + 2304);        // 576 entries  -> floats [2304,4608)
    float*  samp = sm + 4608;                   // [4c][9k][64p] -> 2304 floats
    float*  wdc  = sm + 4608 + 2304;            // [128o][37]    -> 4736 floats

    // ---- corner precompute: 9 k x 64 px ----
    for (int s = tid; s < 576; s += 256) {
        int k = s / 64, p = s % 64;
        int i = i0 + (p >> 5), j = p & 31;
        float dy = g_off[((b * NOFF + 2 * k) * HH + i) * WW + j];
        float dx = g_off[((b * NOFF + 2 * k + 1) * HH + i) * WW + j];
        float mv = g_off[((b * NOFF + 18 + k) * HH + i) * WW + j];
        float msk = 1.f / (1.f + expf(-mv));
        float py = (float)(i + (k / 3) - 1) + dy;
        float px = (float)(j + (k % 3) - 1) + dx;
        float fy = floorf(py), fx = floorf(px);
        float wy = py - fy, wx = px - fx;

        int4 id; float4 wv;
        {
            float yc = fy, xc = fx;
            bool v = (yc >= 0.f) && (yc <= 31.f) && (xc >= 0.f) && (xc <= 31.f);
            int yi = min(max((int)yc, 0), 31), xi = min(max((int)xc, 0), 31);
            id.x = yi * WW + xi; wv.x = (1.f - wy) * (1.f - wx) * (v ? msk : 0.f);
        }
        {
            float yc = fy, xc = fx + 1.f;
            bool v = (yc >= 0.f) && (yc <= 31.f) && (xc >= 0.f) && (xc <= 31.f);
            int yi = min(max((int)yc, 0), 31), xi = min(max((int)xc, 0), 31);
            id.y = yi * WW + xi; wv.y = (1.f - wy) * wx * (v ? msk : 0.f);
        }
        {
            float yc = fy + 1.f, xc = fx;
            bool v = (yc >= 0.f) && (yc <= 31.f) && (xc >= 0.f) && (xc <= 31.f);
            int yi = min(max((int)yc, 0), 31), xi = min(max((int)xc, 0), 31);
            id.z = yi * WW + xi; wv.z = wy * (1.f - wx) * (v ? msk : 0.f);
        }
        {
            float yc = fy + 1.f, xc = fx + 1.f;
            bool v = (yc >= 0.f) && (yc <= 31.f) && (xc >= 0.f) && (xc <= 31.f);
            int yi = min(max((int)yc, 0), 31), xi = min(max((int)xc, 0), 31);
            id.w = yi * WW + xi; wv.w = wy * wx * (v ? msk : 0.f);
        }
        idxs[s] = id; wgts[s] = wv;
    }
    __syncthreads();

    float acc[32];
#pragma unroll
    for (int q = 0; q < 32; q++) acc[q] = 0.f;

    const int o  = tid & 127;
    const int ph = tid >> 7;

    for (int c0 = 0; c0 < CIN; c0 += 4) {
        // stage weights: w_dcn[o][c0..c0+3][0..8] -> wdc[o][36] (stride 37)
        {
            int oo = tid >> 1, half = tid & 1;
            const float* src = w_dcn + (oo * CIN + c0) * 9 + half * 18;
            float* dst = wdc + oo * 37 + half * 18;
#pragma unroll
            for (int n = 0; n < 18; n++) dst[n] = src[n];
        }
        // sample A-tile: 4 c x 9 k x 64 px
        for (int s = tid; s < 2304; s += 256) {
            int cc = s / 576, r = s % 576;
            const float* xp = x + ((size_t)(b * CIN + c0 + cc) << 10);
            int4 id = idxs[r]; float4 wv = wgts[r];
            samp[cc * 576 + r] = fmaf(wv.x, xp[id.x],
                                 fmaf(wv.y, xp[id.y],
                                 fmaf(wv.z, xp[id.z], wv.w * xp[id.w])));
        }
        __syncthreads();

#pragma unroll
        for (int cc = 0; cc < 4; cc++) {
#pragma unroll
            for (int k = 0; k < 9; k++) {
                float wv = wdc[o * 37 + cc * 9 + k];
                const float4* sp = (const float4*)&samp[(cc * 9 + k) * 64 + ph * 32];
#pragma unroll
                for (int q = 0; q < 8; q++) {
                    float4 s4 = sp[q];
                    acc[q * 4 + 0] = fmaf(wv, s4.x, acc[q * 4 + 0]);
                    acc[q * 4 + 1] = fmaf(wv, s4.y, acc[q * 4 + 1]);
                    acc[q * 4 + 2] = fmaf(wv, s4.z, acc[q * 4 + 2]);
                    acc[q * 4 + 3] = fmaf(wv, s4.w, acc[q * 4 + 3]);
                }
            }
        }
        __syncthreads();
    }

    // epilogue: SMEM transpose for coalesced STG (alias sm, stride 68 = conflict-free)
    float* outs = sm;
#pragma unroll
    for (int q = 0; q < 8; q++)
        *(float4*)&outs[o * 68 + ph * 32 + q * 4] =
            make_float4(acc[q * 4], acc[q * 4 + 1], acc[q * 4 + 2], acc[q * 4 + 3]);
    __syncthreads();
    for (int r = 0; r < 32; r++) {
        int e = tid + r * 256;
        int oo = e >> 6, p = e & 63;
        g_y0[(b * CO + oo) * (HH * WW) + i0 * 32 + p] = outs[oo * 68 + p];
    }
}

// =================================================================================
// Kernel 3/5: BN stats. One block per channel; computes folded scale/shift.
// which=0: over g_y0 (plane 1024); which=1: over g_y1 (plane 4096).
// =================================================================================
__global__ void k_bnstats(int which, const float* __restrict__ gamma,
                          const float* __restrict__ beta) {
    const int c = blockIdx.x;
    const float* src = which ? g_y1 : g_y0;
    const int plane = which ? (HO * WO) : (HH * WW);
    const int npc = plane * BB;
    const int p4c = plane >> 2;

    float s = 0.f, s2 = 0.f;
    for (int e = threadIdx.x; e < (npc >> 2); e += 256) {
        int bb = e / p4c, p4 = e % p4c;
        float4 v = *(const float4*)&src[((size_t)(bb * CO + c)) * plane + p4 * 4];
        s  += v.x + v.y + v.z + v.w;
        s2 += v.x * v.x + v.y * v.y + v.z * v.z + v.w * v.w;
    }
#pragma unroll
    for (int off = 16; off > 0; off >>= 1) {
        s  += __shfl_down_sync(0xffffffffu, s, off);
        s2 += __shfl_down_sync(0xffffffffu, s2, off);
    }
    __shared__ float red[64];
    int wid = threadIdx.x >> 5, lane = threadIdx.x & 31;
    if (lane == 0) { red[wid] = s; red[wid + 32] = s2; }
    __syncthreads();
    if (threadIdx.x == 0) {
        float S = 0.f, S2 = 0.f;
#pragma unroll
        for (int w = 0; w < 8; w++) { S += red[w]; S2 += red[w + 32]; }
        float inv = 1.f / (float)npc;
        float mu = S * inv;
        float var = S2 * inv - mu * mu;
        float rs = rsqrtf(var + 1e-5f);
        float sc = rs * gamma[c];
        if (which) { g_sc2[c] = sc; g_sh2[c] = beta[c] - mu * sc; }
        else       { g_sc1[c] = sc; g_sh1[c] = beta[c] - mu * sc; }
    }
}

// =================================================================================
// Kernel 4: transposed conv 4x4 stride 2 pad 1, fused BN1+ReLU on input read.
// Block = (b, oy). out[oy] reads rows iy0=(oy+1)>>1 (kh0=oy-2*iy0+1) and iy0-1 (kh0+2).
// Thread: o = tid&127, oxg = tid>>7; acc over 32 ox. SMEM-transpose epilogue.
// =================================================================================
__global__ void __launch_bounds__(256) k_convt(const float* __restrict__ w_up) {
    const int oy = blockIdx.x;
    const int b  = blockIdx.y;
    const int tid = threadIdx.x;
    const int o   = tid & 127;
    const int oxg = tid >> 7;

    __shared__ float sm[8736];      // yin [8][2][34] = 544, wsh [8][8][128] = 8192
    float* yin = sm;
    float* wsh = sm + 544;

    const int iy0 = (oy + 1) >> 1;
    const int kh0 = oy - 2 * iy0 + 1;
    const int iy1 = iy0 - 1;
    const int kh1 = kh0 + 2;
    const bool v0 = (iy0 < HH);
    const bool v1 = (iy1 >= 0);

    float acc[32];
#pragma unroll
    for (int q = 0; q < 32; q++) acc[q] = 0.f;

    for (int i0 = 0; i0 < CO; i0 += 8) {
        // stage normalized+relu input rows (zeros outside image)
        for (int s = tid; s < 544; s += 256) {
            int ii = s / 68, slot = (s % 68) / 34, col = s % 34;
            int ix = col - 1;
            int iy = slot == 0 ? iy0 : iy1;
            bool vv = (slot == 0 ? v0 : v1) && (ix >= 0) && (ix < WW);
            float v = 0.f;
            if (vv) {
                int ic = i0 + ii;
                float raw = g_y0[((b * CO + ic) * HH + iy) * WW + ix];
                v = fmaxf(fmaf(raw, g_sc1[ic], g_sh1[ic]), 0.f);
            }
            yin[(ii * 2 + slot) * 34 + col] = v;
        }
        // stage weights: w_up[i][o][kh0*4..], [kh1*4..] -> wsh[i][q][o]
#pragma unroll
        for (int n = 0; n < 4; n++) {
            int pair = tid + n * 256;
            int ii = pair >> 7, oo = pair & 127;
            const float* wp = w_up + ((size_t)((i0 + ii) * CO + oo)) * 16;
            float4 a = *(const float4*)(wp + kh0 * 4);
            float4 bq = *(const float4*)(wp + kh1 * 4);
            wsh[(ii * 8 + 0) * 128 + oo] = a.x;
            wsh[(ii * 8 + 1) * 128 + oo] = a.y;
            wsh[(ii * 8 + 2) * 128 + oo] = a.z;
            wsh[(ii * 8 + 3) * 128 + oo] = a.w;
            wsh[(ii * 8 + 4) * 128 + oo] = bq.x;
            wsh[(ii * 8 + 5) * 128 + oo] = bq.y;
            wsh[(ii * 8 + 6) * 128 + oo] = bq.z;
            wsh[(ii * 8 + 7) * 128 + oo] = bq.w;
        }
        __syncthreads();

#pragma unroll
        for (int ii = 0; ii < 8; ii++) {
            float wA0 = wsh[(ii * 8 + 0) * 128 + o];
            float wA1 = wsh[(ii * 8 + 1) * 128 + o];
            float wA2 = wsh[(ii * 8 + 2) * 128 + o];
            float wA3 = wsh[(ii * 8 + 3) * 128 + o];
            float wB0 = wsh[(ii * 8 + 4) * 128 + o];
            float wB1 = wsh[(ii * 8 + 5) * 128 + o];
            float wB2 = wsh[(ii * 8 + 6) * 128 + o];
            float wB3 = wsh[(ii * 8 + 7) * 128 + o];
            const float* y0r = &yin[(ii * 2 + 0) * 34];
            const float* y1r = &yin[(ii * 2 + 1) * 34];
            const int xb = oxg * 16;
#pragma unroll
            for (int mh = 0; mh < 16; mh++) {
                int xx = xb + mh;
                float p0 = y0r[xx], p1 = y0r[xx + 1], p2 = y0r[xx + 2];
                float q0 = y1r[xx], q1 = y1r[xx + 1], q2 = y1r[xx + 2];
                // even ox = oxg*32 + 2*mh : taps (kw1,kw3) @ ix0=xx, ix1=xx-1 -> cols xx+1, xx
                acc[2 * mh]     = fmaf(p1, wA1, fmaf(p0, wA3,
                                  fmaf(q1, wB1, fmaf(q0, wB3, acc[2 * mh]))));
                // odd ox: taps (kw0,kw2) @ cols xx+2, xx+1
                acc[2 * mh + 1] = fmaf(p2, wA0, fmaf(p1, wA2,
                                  fmaf(q2, wB0, fmaf(q1, wB2, acc[2 * mh + 1]))));
            }
        }
        __syncthreads();
    }

    // epilogue transpose (alias sm; stride 68 conflict-free)
    float* outs = sm;
#pragma unroll
    for (int q = 0; q < 8; q++)
        *(float4*)&outs[o * 68 + oxg * 32 + q * 4] =
            make_float4(acc[q * 4], acc[q * 4 + 1], acc[q * 4 + 2], acc[q * 4 + 3]);
    __syncthreads();
    for (int r = 0; r < 32; r++) {
        int e = tid + r * 256;
        int oo = e >> 6, ox = e & 63;
        g_y1[((size_t)(b * CO + oo) * HO + oy) * WO + ox] = outs[oo * 68 + ox];
    }
}

// =================================================================================
// Kernel 6: final BN2 + ReLU -> d_out
// =================================================================================
__global__ void k_bnapply(float* __restrict__ out) {
    int idx4 = blockIdx.x * 256 + threadIdx.x;   // 2,097,152 float4s
    int c = (idx4 >> 10) & 127;
    float4 v = *(const float4*)&g_y1[(size_t)idx4 * 4];
    float sc = g_sc2[c], sh = g_sh2[c];
    v.x = fmaxf(fmaf(v.x, sc, sh), 0.f);
    v.y = fmaxf(fmaf(v.y, sc, sh), 0.f);
    v.z = fmaxf(fmaf(v.z, sc, sh), 0.f);
    v.w = fmaxf(fmaf(v.w, sc, sh), 0.f);
    *(float4*)&out[(size_t)idx4 * 4] = v;
}

// =================================================================================
extern "C" void kernel_launch(void* const* d_in, const int* in_sizes, int n_in,
                              void* d_out, int out_size) {
    const float* x     = (const float*)d_in[0];
    const float* w_off = (const float*)d_in[1];
    const float* b_off = (const float*)d_in[2];
    const float* w_dcn = (const float*)d_in[3];
    // d_in[4] = b_dcn: cancels exactly through BN1 (per-channel constant) — unused
    const float* g1    = (const float*)d_in[5];
    const float* bt1   = (const float*)d_in[6];
    const float* w_up  = (const float*)d_in[7];
    const float* g2    = (const float*)d_in[8];
    const float* bt2   = (const float*)d_in[9];
    float* out = (float*)d_out;

    k_offset <<<dim3(HH, BB), dim3(32, 8)>>>(x, w_off, b_off);
    k_deform <<<dim3(HH / 2, BB), 256>>>(x, w_dcn);
    k_bnstats<<<CO, 256>>>(0, g1, bt1);
    k_convt  <<<dim3(HO, BB), 256>>>(w_up);
    k_bnstats<<<CO, 256>>>(1, g2, bt2);
    k_bnapply<<<(BB * CO * HO * WO / 4) / 256, 256>>>(out);
}

// round 2
// speedup vs baseline: 1.1789x; 1.1789x over previous
#include <cuda_runtime.h>
#include <math.h>

#define BB 16
#define CIN 256
#define CO 128
#define HH 32
#define WW 32
#define HO 64
#define WO 64
#define NOFF 27

typedef unsigned long long u64;

// ---------------- f32x2 helpers (sm_103a packed fp32 FMA) ----------------
__device__ __forceinline__ u64 pack2(float x, float y) {
    u64 r; asm("mov.b64 %0,{%1,%2};" : "=l"(r) : "f"(x), "f"(y)); return r;
}
__device__ __forceinline__ void fma2(u64& d, u64 a, u64 b) {
    asm("fma.rn.f32x2 %0,%1,%2,%0;" : "+l"(d) : "l"(a), "l"(b));
}
__device__ __forceinline__ float2 unpack2(u64 v) {
    float2 f; asm("mov.b64 {%0,%1},%2;" : "=f"(f.x), "=f"(f.y) : "l"(v)); return f;
}

// ---------------- scratch (static device globals; no allocation) ----------------
__device__ float g_off[BB * NOFF * HH * WW];   // offset-conv output (27 ch)
__device__ float g_y0[BB * CO * HH * WW];      // deform-conv output (pre-BN)
__device__ float g_y1[BB * CO * HO * WO];      // transposed-conv output (pre-BN)
__device__ float g_sc1[CO], g_sh1[CO];         // BN1 folded scale/shift
__device__ float g_sc2[CO], g_sh2[CO];         // BN2 folded scale/shift
__device__ float g_wT[64 * 36 * 128];          // w_dcn re-layout [chunk][tap36][o]
__device__ float g_wT2[16 * 128 * 128];        // w_up re-layout [tap16][i][o]

// =================================================================================
// Weight prep kernels (tiny; make main-kernel staging fully coalesced)
// =================================================================================
__global__ void k_wprep(const float* __restrict__ w_dcn) {
    int idx = blockIdx.x * 256 + threadIdx.x;          // 64*36*128 = 294912
    int o = idx & 127;
    int t = (idx >> 7) % 36;
    int chunk = idx / 4608;
    int c = chunk * 4 + t / 9;
    int k = t % 9;
    g_wT[idx] = w_dcn[(o * CIN + c) * 9 + k];
}
__global__ void k_wprep2(const float* __restrict__ w_up) {
    int idx = blockIdx.x * 256 + threadIdx.x;          // 16*128*128 = 262144
    int o = idx & 127;
    int i = (idx >> 7) & 127;
    int tap = idx >> 14;
    g_wT2[idx] = w_up[(i * CO + o) * 16 + tap];
}

// =================================================================================
// Kernel 1: offset conv 3x3, CIN=256 -> 27 channels. (unchanged; ~70us)
// =================================================================================
__global__ void k_offset(const float* __restrict__ x,
                         const float* __restrict__ w_off,
                         const float* __restrict__ b_off) {
    const int i  = blockIdx.x;
    const int b  = blockIdx.y;
    const int tx = threadIdx.x;
    const int ty = threadIdx.y;
    const int tid = ty * 32 + tx;

    __shared__ float xs[16][3][36];
    __shared__ float ws[16][9][32];

    float a0 = 0.f, a1 = 0.f, a2 = 0.f, a3 = 0.f;

    for (int c0 = 0; c0 < CIN; c0 += 16) {
        for (int s = tid; s < 16 * 3 * 34; s += 256) {
            int c = s / 102, r = (s % 102) / 34, col = s % 34;
            int ii = i + r - 1, jj = col - 1;
            float v = 0.f;
            if (ii >= 0 && ii < HH && jj >= 0 && jj < WW)
                v = x[((b * CIN + c0 + c) * HH + ii) * WW + jj];
            xs[c][r][col] = v;
        }
        for (int s = tid; s < 27 * 16 * 9; s += 256) {
            int oc = s / 144, c = (s % 144) / 9, tap = s % 9;
            ws[c][tap][oc] = w_off[(oc * CIN + c0 + c) * 9 + tap];
        }
        __syncthreads();

        const int tj = ty * 4;
#pragma unroll 4
        for (int c = 0; c < 16; c++) {
#pragma unroll
            for (int kh = 0; kh < 3; kh++) {
                float x0 = xs[c][kh][tj + 0];
                float x1 = xs[c][kh][tj + 1];
                float x2 = xs[c][kh][tj + 2];
                float x3 = xs[c][kh][tj + 3];
                float x4 = xs[c][kh][tj + 4];
                float x5 = xs[c][kh][tj + 5];
                float w0 = ws[c][kh * 3 + 0][tx];
                float w1 = ws[c][kh * 3 + 1][tx];
                float w2 = ws[c][kh * 3 + 2][tx];
                a0 = fmaf(x0, w0, fmaf(x1, w1, fmaf(x2, w2, a0)));
                a1 = fmaf(x1, w0, fmaf(x2, w1, fmaf(x3, w2, a1)));
                a2 = fmaf(x2, w0, fmaf(x3, w1, fmaf(x4, w2, a2)));
                a3 = fmaf(x3, w0, fmaf(x4, w1, fmaf(x5, w2, a3)));
            }
        }
        __syncthreads();
    }
    if (tx < NOFF) {
        float bo = b_off[tx];
        float4 r = make_float4(a0 + bo, a1 + bo, a2 + bo, a3 + bo);
        *(float4*)&g_off[((b * NOFF + tx) * HH + i) * WW + ty * 4] = r;
    }
}

// =================================================================================
// Kernel 2: deformable conv. FFMA2 accumulators, double-buffered sampling,
// weights loaded coalesced to registers from g_wT. b_dcn cancels in BN1.
// =================================================================================
__global__ void __launch_bounds__(256, 3) k_deform(const float* __restrict__ x) {
    const int b  = blockIdx.y;
    const int i0 = blockIdx.x * 2;
    const int tid = threadIdx.x;

    __shared__ float sm[9216];                  // 36.9 KB
    int4*   idxs  = (int4*)sm;                  // floats [0,2304)
    float4* wgts  = (float4*)(sm + 2304);       // floats [2304,4608)
    float*  sampA = sm + 4608;                  // [4608,6912)
    float*  sampB = sm + 6912;                  // [6912,9216)

    // ---- corner precompute: 9 k x 64 px ----
    for (int s = tid; s < 576; s += 256) {
        int k = s / 64, p = s % 64;
        int i = i0 + (p >> 5), j = p & 31;
        float dy = g_off[((b * NOFF + 2 * k) * HH + i) * WW + j];
        float dx = g_off[((b * NOFF + 2 * k + 1) * HH + i) * WW + j];
        float mv = g_off[((b * NOFF + 18 + k) * HH + i) * WW + j];
        float msk = 1.f / (1.f + expf(-mv));
        float py = (float)(i + (k / 3) - 1) + dy;
        float px = (float)(j + (k % 3) - 1) + dx;
        float fy = floorf(py), fx = floorf(px);
        float wy = py - fy, wx = px - fx;

        int4 id; float4 wv;
        {
            bool v = (fy >= 0.f) && (fy <= 31.f) && (fx >= 0.f) && (fx <= 31.f);
            int yi = min(max((int)fy, 0), 31), xi = min(max((int)fx, 0), 31);
            id.x = yi * WW + xi; wv.x = (1.f - wy) * (1.f - wx) * (v ? msk : 0.f);
        }
        {
            float xc = fx + 1.f;
            bool v = (fy >= 0.f) && (fy <= 31.f) && (xc >= 0.f) && (xc <= 31.f);
            int yi = min(max((int)fy, 0), 31), xi = min(max((int)xc, 0), 31);
            id.y = yi * WW + xi; wv.y = (1.f - wy) * wx * (v ? msk : 0.f);
        }
        {
            float yc = fy + 1.f;
            bool v = (yc >= 0.f) && (yc <= 31.f) && (fx >= 0.f) && (fx <= 31.f);
            int yi = min(max((int)yc, 0), 31), xi = min(max((int)fx, 0), 31);
            id.z = yi * WW + xi; wv.z = wy * (1.f - wx) * (v ? msk : 0.f);
        }
        {
            float yc = fy + 1.f, xc = fx + 1.f;
            bool v = (yc >= 0.f) && (yc <= 31.f) && (xc >= 0.f) && (xc <= 31.f);
            int yi = min(max((int)yc, 0), 31), xi = min(max((int)xc, 0), 31);
            id.w = yi * WW + xi; wv.w = wy * wx * (v ? msk : 0.f);
        }
        idxs[s] = id; wgts[s] = wv;
    }
    __syncthreads();

    u64 acc2[16];
#pragma unroll
    for (int q = 0; q < 16; q++) acc2[q] = 0ull;

    const int o  = tid & 127;
    const int ph = tid >> 7;
    const float* xbase = x + ((size_t)(b * CIN) << 10);

    // prologue: stage chunk 0 into sampA
    for (int s = tid; s < 2304; s += 256) {
        int cc = s / 576, r = s % 576;
        const float* xp = xbase + (cc << 10);
        int4 id = idxs[r]; float4 wv = wgts[r];
        sampA[s] = fmaf(wv.x, xp[id.x], fmaf(wv.y, xp[id.y],
                   fmaf(wv.z, xp[id.z], wv.w * xp[id.w])));
    }
    __syncthreads();

    for (int it = 0; it < 64; it++) {
        float* scur = (it & 1) ? sampB : sampA;
        if (it + 1 < 64) {
            float* snxt = (it & 1) ? sampA : sampB;
            const float* xp0 = xbase + ((size_t)(it + 1) << 12);
            for (int s = tid; s < 2304; s += 256) {
                int cc = s / 576, r = s % 576;
                const float* xp = xp0 + (cc << 10);
                int4 id = idxs[r]; float4 wv = wgts[r];
                snxt[s] = fmaf(wv.x, xp[id.x], fmaf(wv.y, xp[id.y],
                          fmaf(wv.z, xp[id.z], wv.w * xp[id.w])));
            }
        }
        const float* wp = g_wT + it * 4608 + o;
#pragma unroll
        for (int cc = 0; cc < 4; cc++) {
            float w[9];
#pragma unroll
            for (int k = 0; k < 9; k++) w[k] = wp[(cc * 9 + k) << 7];
#pragma unroll
            for (int k = 0; k < 9; k++) {
                u64 w2 = pack2(w[k], w[k]);
                const ulonglong2* sp = (const ulonglong2*)&scur[(cc * 9 + k) * 64 + ph * 32];
#pragma unroll
                for (int q = 0; q < 8; q++) {
                    ulonglong2 sv = sp[q];
                    fma2(acc2[2 * q],     sv.x, w2);
                    fma2(acc2[2 * q + 1], sv.y, w2);
                }
            }
        }
        __syncthreads();
    }

    // epilogue: SMEM transpose for coalesced STG (alias sm; stride 68)
    float* outs = sm;
#pragma unroll
    for (int q = 0; q < 8; q++) {
        float2 e0 = unpack2(acc2[2 * q]);
        float2 e1 = unpack2(acc2[2 * q + 1]);
        *(float4*)&outs[o * 68 + ph * 32 + q * 4] = make_float4(e0.x, e0.y, e1.x, e1.y);
    }
    __syncthreads();
    for (int r = 0; r < 32; r++) {
        int e = tid + r * 256;
        int oo = e >> 6, p = e & 63;
        g_y0[(b * CO + oo) * (HH * WW) + i0 * 32 + p] = outs[oo * 68 + p];
    }
}

// =================================================================================
// Kernel 3/5: BN stats -> folded scale/shift (unchanged)
// =================================================================================
__global__ void k_bnstats(int which, const float* __restrict__ gamma,
                          const float* __restrict__ beta) {
    const int c = blockIdx.x;
    const float* src = which ? g_y1 : g_y0;
    const int plane = which ? (HO * WO) : (HH * WW);
    const int npc = plane * BB;
    const int p4c = plane >> 2;

    float s = 0.f, s2 = 0.f;
    for (int e = threadIdx.x; e < (npc >> 2); e += 256) {
        int bb = e / p4c, p4 = e % p4c;
        float4 v = *(const float4*)&src[((size_t)(bb * CO + c)) * plane + p4 * 4];
        s  += v.x + v.y + v.z + v.w;
        s2 += v.x * v.x + v.y * v.y + v.z * v.z + v.w * v.w;
    }
#pragma unroll
    for (int off = 16; off > 0; off >>= 1) {
        s  += __shfl_down_sync(0xffffffffu, s, off);
        s2 += __shfl_down_sync(0xffffffffu, s2, off);
    }
    __shared__ float red[64];
    int wid = threadIdx.x >> 5, lane = threadIdx.x & 31;
    if (lane == 0) { red[wid] = s; red[wid + 32] = s2; }
    __syncthreads();
    if (threadIdx.x == 0) {
        float S = 0.f, S2 = 0.f;
#pragma unroll
        for (int w = 0; w < 8; w++) { S += red[w]; S2 += red[w + 32]; }
        float inv = 1.f / (float)npc;
        float mu = S * inv;
        float var = S2 * inv - mu * mu;
        float rs = rsqrtf(var + 1e-5f);
        float sc = rs * gamma[c];
        if (which) { g_sc2[c] = sc; g_sh2[c] = beta[c] - mu * sc; }
        else       { g_sc1[c] = sc; g_sh1[c] = beta[c] - mu * sc; }
    }
}

// =================================================================================
// Kernel 4: transposed conv 4x4 s2 p1, fused BN1+ReLU input, FFMA2 over ox-pairs,
// double-buffered staging (1 sync/iter), coalesced weight staging from g_wT2.
// =================================================================================
__global__ void __launch_bounds__(256, 3) k_convt() {
    const int oy = blockIdx.x;
    const int b  = blockIdx.y;
    const int tid = threadIdx.x;
    const int o   = tid & 127;
    const int oxg = tid >> 7;
    const int xb  = oxg * 16;

    __shared__ float sm[17536];     // yin 2x576 + wsh 2x8192 = 70.1 KB
    float* yinb[2] = { sm, sm + 576 };
    float* wshb[2] = { sm + 1152, sm + 1152 + 8192 };

    const int iy0 = (oy + 1) >> 1;
    const int kh0 = oy - 2 * iy0 + 1;
    const int iy1 = iy0 - 1;
    const int kh1 = kh0 + 2;
    const bool v0 = (iy0 < HH);
    const bool v1 = (iy1 >= 0);

    u64 acc_e[8], acc_o[8];
#pragma unroll
    for (int q = 0; q < 8; q++) { acc_e[q] = 0ull; acc_o[q] = 0ull; }

    // ---- staging helper (macro-expanded inline) ----
#define STAGE(i0v, buf)                                                          \
    {                                                                            \
        float* yin = yinb[buf];                                                  \
        float* wsh = wshb[buf];                                                  \
        for (int s = tid; s < 576; s += 256) {                                   \
            int ii = s / 72; int rem = s % 72;                                   \
            int slot = rem / 36; int col = rem % 36;                             \
            int ix = col - 1;                                                    \
            int iy = slot == 0 ? iy0 : iy1;                                      \
            float v = 0.f;                                                       \
            if (col < 34 && (slot == 0 ? v0 : v1) && ix >= 0 && ix < WW) {       \
                int ic = (i0v) + ii;                                             \
                float raw = g_y0[((b * CO + ic) * HH + iy) * WW + ix];           \
                v = fmaxf(fmaf(raw, g_sc1[ic], g_sh1[ic]), 0.f);                 \
            }                                                                    \
            yin[s] = v;                                                          \
        }                                                                        \
        for (int n = 0; n < 8; n++) {                                            \
            int s4 = tid + n * 256;                                              \
            int t = s4 >> 8;                                                     \
            int rem = s4 & 255;                                                  \
            int tap = (t < 4) ? (kh0 * 4 + t) : (kh1 * 4 + (t - 4));             \
            float4 v = *(const float4*)&g_wT2[(tap << 14) + ((i0v) << 7) + rem * 4]; \
            *(float4*)&wsh[s4 * 4] = v;                                          \
        }                                                                        \
    }

    STAGE(0, 0);

    for (int itn = 0; itn < 16; itn++) {
        __syncthreads();
        if (itn + 1 < 16) STAGE((itn + 1) * 8, (itn + 1) & 1);

        const int buf = itn & 1;
        const float* yin = yinb[buf];
        const float* wsh = wshb[buf];
#pragma unroll
        for (int ii = 0; ii < 8; ii++) {
#pragma unroll
            for (int r = 0; r < 2; r++) {
                float w0 = wsh[((r * 4 + 0) * 8 + ii) * 128 + o];
                float w1 = wsh[((r * 4 + 1) * 8 + ii) * 128 + o];
                float w2 = wsh[((r * 4 + 2) * 8 + ii) * 128 + o];
                float w3 = wsh[((r * 4 + 3) * 8 + ii) * 128 + o];
                u64 w0d = pack2(w0, w0);
                u64 w1d = pack2(w1, w1);
                u64 w2d = pack2(w2, w2);
                u64 w3d = pack2(w3, w3);
                const float* yr = &yin[(ii * 2 + r) * 36 + xb];
                float yv[18];
                float4 t0 = *(const float4*)(yr);
                float4 t1 = *(const float4*)(yr + 4);
                float4 t2 = *(const float4*)(yr + 8);
                float4 t3 = *(const float4*)(yr + 12);
                yv[0] = t0.x; yv[1] = t0.y; yv[2] = t0.z; yv[3] = t0.w;
                yv[4] = t1.x; yv[5] = t1.y; yv[6] = t1.z; yv[7] = t1.w;
                yv[8] = t2.x; yv[9] = t2.y; yv[10] = t2.z; yv[11] = t2.w;
                yv[12] = t3.x; yv[13] = t3.y; yv[14] = t3.z; yv[15] = t3.w;
                yv[16] = yr[16]; yv[17] = yr[17];
#pragma unroll
                for (int s = 0; s < 8; s++) {
                    const int c = 2 * s;
                    u64 P0 = pack2(yv[c],     yv[c + 1]);
                    u64 P1 = pack2(yv[c + 1], yv[c + 2]);
                    u64 P2 = pack2(yv[c + 2], yv[c + 3]);
                    fma2(acc_e[s], P1, w1d);
                    fma2(acc_e[s], P0, w3d);
                    fma2(acc_o[s], P2, w0d);
                    fma2(acc_o[s], P1, w2d);
                }
            }
        }
    }
#undef STAGE

    __syncthreads();
    // epilogue transpose (alias sm; stride 68 conflict-free)
    float* outs = sm;
#pragma unroll
    for (int s = 0; s < 8; s++) {
        float2 e = unpack2(acc_e[s]);
        float2 d = unpack2(acc_o[s]);
        *(float4*)&outs[o * 68 + oxg * 32 + 4 * s] = make_float4(e.x, d.x, e.y, d.y);
    }
    __syncthreads();
    for (int r = 0; r < 32; r++) {
        int e = tid + r * 256;
        int oo = e >> 6, ox = e & 63;
        g_y1[((size_t)(b * CO + oo) * HO + oy) * WO + ox] = outs[oo * 68 + ox];
    }
}

// =================================================================================
// Kernel 6: final BN2 + ReLU -> d_out
// =================================================================================
__global__ void k_bnapply(float* __restrict__ out) {
    int idx4 = blockIdx.x * 256 + threadIdx.x;
    int c = (idx4 >> 10) & 127;
    float4 v = *(const float4*)&g_y1[(size_t)idx4 * 4];
    float sc = g_sc2[c], sh = g_sh2[c];
    v.x = fmaxf(fmaf(v.x, sc, sh), 0.f);
    v.y = fmaxf(fmaf(v.y, sc, sh), 0.f);
    v.z = fmaxf(fmaf(v.z, sc, sh), 0.f);
    v.w = fmaxf(fmaf(v.w, sc, sh), 0.f);
    *(float4*)&out[(size_t)idx4 * 4] = v;
}

// =================================================================================
extern "C" void kernel_launch(void* const* d_in, const int* in_sizes, int n_in,
                              void* d_out, int out_size) {
    const float* x     = (const float*)d_in[0];
    const float* w_off = (const float*)d_in[1];
    const float* b_off = (const float*)d_in[2];
    const float* w_dcn = (const float*)d_in[3];
    // d_in[4] = b_dcn: cancels exactly through BN1 — unused
    const float* g1    = (const float*)d_in[5];
    const float* bt1   = (const float*)d_in[6];
    const float* w_up  = (const float*)d_in[7];
    const float* g2    = (const float*)d_in[8];
    const float* bt2   = (const float*)d_in[9];
    float* out = (float*)d_out;

    k_wprep  <<<1152, 256>>>(w_dcn);
    k_wprep2 <<<1024, 256>>>(w_up);
    k_offset <<<dim3(HH, BB), dim3(32, 8)>>>(x, w_off, b_off);
    k_deform <<<dim3(HH / 2, BB), 256>>>(x);
    k_bnstats<<<CO, 256>>>(0, g1, bt1);
    k_convt  <<<dim3(HO, BB), 256>>>();
    k_bnstats<<<CO, 256>>>(1, g2, bt2);
    k_bnapply<<<(BB * CO * HO * WO / 4) / 256, 256>>>(out);
}